// round 15
// baseline (speedup 1.0000x reference)
#include <cuda_runtime.h>
#include <math.h>

#define NTOK 512
#define NH   12
#define NCH  16
#define NPQ  4
#define NPV  8
#define NCS  384
#define NCZ  128
#define NHC  192
#define NOUTD 2112
#define NNN  (NTOK*NTOK)

typedef unsigned long long ull;

// ---- f32x2 packed-FMA helpers (Blackwell) ----------------------------------
__device__ __forceinline__ ull pk2(float a, float b) {
    ull r;
    asm("mov.b64 %0, {%1,%2};" : "=l"(r)
        : "r"(__float_as_uint(a)), "r"(__float_as_uint(b)));
    return r;
}
__device__ __forceinline__ ull fmaf2(ull a, ull b, ull c) {
    ull d;
    asm("fma.rn.f32x2 %0, %1, %2, %3;" : "=l"(d) : "l"(a), "l"(b), "l"(c));
    return d;
}
__device__ __forceinline__ ull addf2(ull a, ull b) {
    ull d;
    asm("add.rn.f32x2 %0, %1, %2;" : "=l"(d) : "l"(a), "l"(b));
    return d;
}
__device__ __forceinline__ float2 upk2(ull a) {
    unsigned lo_, hi_;
    asm("mov.b64 {%0,%1}, %2;" : "=r"(lo_), "=r"(hi_) : "l"(a));
    return make_float2(__uint_as_float(lo_), __uint_as_float(hi_));
}
#define LL(x) __double_as_longlong(x)
#define DD(x) __longlong_as_double(x)

// ---------------- scratch ----------------------------------------------------
__device__ float g_qraw[NTOK*NHC];
__device__ float g_kvraw[NTOK*2*NHC];
__device__ float g_qpraw[NTOK*NH*NPQ*3];
__device__ float g_kvpraw[NTOK*NH*(NPQ+NPV)*3];
__device__ float g_qaug[NTOK*NH*32];
__device__ float g_kaugT[NH*32*NTOK];
__device__ float g_vcat[NH*NTOK*40];
__device__ float g_bpairT[NH*NNN];               // 0.577*(z@Wb+bb) [h][i][j]
__device__ float g_qk[NH*NNN];                   // [h][i][j]
__device__ float g_attn[NH*NNN];                 // [h][i][j]
__device__ float g_cat[NTOK*NOUTD];
__device__ float g_fpart[6*NTOK*NCS];
__device__ float g_ovhp[4*NH*NTOK*40];

// ---------------- Kernel 1: projections from s (f32x2, 32 tokens/blk) -------
__global__ void __launch_bounds__(256)
proj_kernel(const float* __restrict__ s,
            const float* __restrict__ Wq,   const float* __restrict__ bq,
            const float* __restrict__ Wkv,  const float* __restrict__ bkv,
            const float* __restrict__ Wqp,  const float* __restrict__ bqp,
            const float* __restrict__ Wkvp, const float* __restrict__ bkvp)
{
    __shared__ float s_s[32][384];
    const int tid = threadIdx.x;
    const int i0  = blockIdx.x * 32;
    for (int idx = tid; idx < 32*384; idx += 256)
        s_s[idx/384][idx%384] = s[i0*384 + idx];
    __syncthreads();

    const float* W; const float* bias; float* out; int Nc; int ct;
    const int by = blockIdx.y;
    if      (by < 3)  { W=Wq;   bias=bq;   out=g_qraw;   Nc=192; ct=by;    }
    else if (by < 9)  { W=Wkv;  bias=bkv;  out=g_kvraw;  Nc=384; ct=by-3;  }
    else if (by < 12) { W=Wqp;  bias=bqp;  out=g_qpraw;  Nc=144; ct=by-9;  }
    else              { W=Wkvp; bias=bkvp; out=g_kvpraw; Nc=432; ct=by-12; }

    const int col = ct*64 + (tid & 63);
    if (col >= Nc) return;
    const int t0 = (tid >> 6) * 8;

    ull a[8];
    #pragma unroll
    for (int rr = 0; rr < 8; rr++) a[rr] = 0ULL;

    #pragma unroll 2
    for (int k = 0; k < 384; k += 4) {
        const float w0 = W[(k+0)*Nc + col];
        const float w1 = W[(k+1)*Nc + col];
        const float w2 = W[(k+2)*Nc + col];
        const float w3 = W[(k+3)*Nc + col];
        const ull wp01 = pk2(w0,w1), wp23 = pk2(w2,w3);
        #pragma unroll
        for (int rr = 0; rr < 8; rr++) {
            const double2 v = *(const double2*)&s_s[t0+rr][k];
            a[rr] = fmaf2(LL(v.x), wp01, a[rr]);
            a[rr] = fmaf2(LL(v.y), wp23, a[rr]);
        }
    }
    const float bv = bias[col];
    #pragma unroll
    for (int rr = 0; rr < 8; rr++) {
        const float2 u = upk2(a[rr]);
        out[(i0+t0+rr)*Nc + col] = u.x + u.y + bv;
    }
}

// ---------------- Kernel 2: rotate points, build Q'/K'^T/Vcat ---------------
__global__ void prep_kernel(const float* __restrict__ rot, const float* __restrict__ trans,
                            const float* __restrict__ hwts)
{
    __shared__ float qpts_s[144];
    __shared__ float kpts_s[144];
    __shared__ float vpts_s[288];
    __shared__ float shw[NH];
    const int i = blockIdx.x;
    const int tid = threadIdx.x;

    if (tid < NH)
        shw[tid] = log1pf(__expf(hwts[tid])) * 0.1360827635f;

    if (tid < 192) {
        const int m = tid;
        const float* R = rot + i*9;
        const float tx = trans[i*3+0], ty = trans[i*3+1], tz = trans[i*3+2];
        float x, y, zc; float* dst;
        if (m < 48) {
            const float* src = g_qpraw + i*144;
            x = src[m]; y = src[48+m]; zc = src[96+m];
            dst = qpts_s + m*3;
        } else {
            const int mm = m - 48;
            const float* src = g_kvpraw + i*432;
            x = src[mm]; y = src[144+mm]; zc = src[288+mm];
            const int h = mm / 12, pp = mm % 12;
            if (pp < 4) dst = kpts_s + (h*4+pp)*3;
            else        dst = vpts_s + (h*8 + pp-4)*3;
        }
        dst[0] = R[0]*x + R[1]*y + R[2]*zc + tx;
        dst[1] = R[3]*x + R[4]*y + R[5]*zc + ty;
        dst[2] = R[6]*x + R[7]*y + R[8]*zc + tz;
    }
    __syncthreads();

    for (int idx = tid; idx < 384; idx += 256) {
        const int h = idx >> 5, d = idx & 31;
        const float hw = shw[h];
        float qv, kv;
        if (d < 16) {
            qv = 0.1443375673f * g_qraw[i*NHC + h*16 + d];
            kv = g_kvraw[i*384 + h*32 + d];
        } else if (d < 28) {
            qv = hw * qpts_s[h*12 + d-16];
            kv = kpts_s[h*12 + d-16];
        } else if (d == 28) {
            float qn = 0.f;
            #pragma unroll
            for (int e = 0; e < 12; e++) { const float t = qpts_s[h*12+e]; qn += t*t; }
            qv = -0.5f * hw * qn;
            kv = 1.0f;
        } else if (d == 29) {
            qv = 1.0f;
            float kn = 0.f;
            #pragma unroll
            for (int e = 0; e < 12; e++) { const float t = kpts_s[h*12+e]; kn += t*t; }
            kv = -0.5f * hw * kn;
        } else { qv = 0.f; kv = 0.f; }
        g_qaug[(i*NH + h)*32 + d] = qv;
        g_kaugT[(h*32 + d)*NTOK + i] = kv;
    }

    for (int idx = tid; idx < 480; idx += 256) {
        const int h = idx / 40, d = idx % 40;
        const float v = (d < 16) ? g_kvraw[i*384 + h*32 + 16 + d]
                                 : vpts_s[h*24 + d-16];
        g_vcat[(h*NTOK + i)*40 + d] = v;
    }
}

// ---------------- Kernel 3 (FAT): qk tiles + bpair slabs (full-line z) ------
// blocks [0,768): qk 64x64 tiles; blocks [768, 768+8192): bpair 32-row slabs.
__global__ void __launch_bounds__(256)
qkbp_kernel(const float* __restrict__ z, const float* __restrict__ Wb,
            const float* __restrict__ bb)
{
    const int tid = threadIdx.x;

    if (blockIdx.x < 768) {
        // ---- qk tile ----
        __shared__ float QsT[32][68];
        __shared__ float Ks[32][68];
        const int bx = blockIdx.x;
        const int j0 = (bx & 7) * 64;
        const int i0 = ((bx >> 3) & 7) * 64;
        const int h  = bx >> 6;

        for (int idx = tid; idx < 2048; idx += 256) {
            const int r = idx >> 5, d = idx & 31;
            QsT[d][r] = g_qaug[((i0+r)*NH + h)*32 + d];
        }
        for (int idx = tid; idx < 2048; idx += 256) {
            const int d = idx >> 6, j = idx & 63;
            Ks[d][j] = g_kaugT[(h*32 + d)*NTOK + j0 + j];
        }
        __syncthreads();

        const int ty = tid >> 4, tx = tid & 15;
        ull acc[4][2];
        #pragma unroll
        for (int rr = 0; rr < 4; rr++) { acc[rr][0] = 0ULL; acc[rr][1] = 0ULL; }

        #pragma unroll
        for (int d = 0; d < 32; d++) {
            const double2 kd = *(const double2*)&Ks[d][tx*4];
            const ull k01 = LL(kd.x), k23 = LL(kd.y);
            const float4 qa = *(const float4*)&QsT[d][ty*4];
            ull dr;
            dr = pk2(qa.x,qa.x); acc[0][0]=fmaf2(dr,k01,acc[0][0]); acc[0][1]=fmaf2(dr,k23,acc[0][1]);
            dr = pk2(qa.y,qa.y); acc[1][0]=fmaf2(dr,k01,acc[1][0]); acc[1][1]=fmaf2(dr,k23,acc[1][1]);
            dr = pk2(qa.z,qa.z); acc[2][0]=fmaf2(dr,k01,acc[2][0]); acc[2][1]=fmaf2(dr,k23,acc[2][1]);
            dr = pk2(qa.w,qa.w); acc[3][0]=fmaf2(dr,k01,acc[3][0]); acc[3][1]=fmaf2(dr,k23,acc[3][1]);
        }
        #pragma unroll
        for (int rr = 0; rr < 4; rr++) {
            double2 st = make_double2(DD(acc[rr][0]), DD(acc[rr][1]));
            *(double2*)&g_qk[(size_t)(h*NTOK + i0 + ty*4+rr)*NTOK + j0 + tx*4] = st;
        }
    } else {
        // ---- bpair slab: 32 rows, full-line z loads ----
        // lane: e = l&7 (channel eighth), rw = l>>3 (row-in-4)
        // warp: h0 = (w&1)*6, rbase = (w>>1)*8; thread rows r0, r0+4.
        __shared__ float wbT[NH][128];   // 6 KB
        __shared__ float tr[32][13];     // 1.7 KB
        const int row0 = (blockIdx.x - 768) * 32;
        const int i  = row0 >> 9;
        const int j0 = row0 & 511;

        for (int idx = tid; idx < NH*128; idx += 256) {
            const int h = idx >> 7, c = idx & 127;
            wbT[h][c] = Wb[c*NH + h];
        }
        __syncthreads();

        const int l = tid & 31, w = tid >> 5;
        const int e  = l & 7;
        const int rw = l >> 3;
        const int h0 = (w & 1) * 6;
        const int r0 = (w >> 1) * 8 + rw;       // rows r0, r0+4

        const float* zr = z + (size_t)(row0 + r0)*NCZ + e*4;
        double2 zA[4], zB[4];
        #pragma unroll
        for (int it = 0; it < 4; it++) {
            zA[it] = *(const double2*)(zr + it*32);
            zB[it] = *(const double2*)(zr + 4*NCZ + it*32);
        }

        ull accA[6], accB[6];
        #pragma unroll
        for (int hh = 0; hh < 6; hh++) { accA[hh] = 0ULL; accB[hh] = 0ULL; }

        #pragma unroll
        for (int it = 0; it < 4; it++) {
            const ull a01 = LL(zA[it].x), a23 = LL(zA[it].y);
            const ull b01 = LL(zB[it].x), b23 = LL(zB[it].y);
            const int cbase = it*32 + e*4;
            #pragma unroll
            for (int hh = 0; hh < 6; hh++) {
                const double2 wd = *(const double2*)&wbT[h0+hh][cbase];
                const ull w01 = LL(wd.x), w23 = LL(wd.y);
                accA[hh] = fmaf2(a01, w01, accA[hh]);
                accA[hh] = fmaf2(a23, w23, accA[hh]);
                accB[hh] = fmaf2(b01, w01, accB[hh]);
                accB[hh] = fmaf2(b23, w23, accB[hh]);
            }
        }
        #pragma unroll
        for (int hh = 0; hh < 6; hh++) {
            const float2 ua = upk2(accA[hh]);
            float va = ua.x + ua.y;
            va += __shfl_xor_sync(0xffffffffu, va, 1);
            va += __shfl_xor_sync(0xffffffffu, va, 2);
            va += __shfl_xor_sync(0xffffffffu, va, 4);
            const float2 ub = upk2(accB[hh]);
            float vb = ub.x + ub.y;
            vb += __shfl_xor_sync(0xffffffffu, vb, 1);
            vb += __shfl_xor_sync(0xffffffffu, vb, 2);
            vb += __shfl_xor_sync(0xffffffffu, vb, 4);
            if (e == 0) {
                tr[r0][h0+hh]     = va;
                tr[r0+4][h0+hh]   = vb;
            }
        }
        __syncthreads();

        for (int o = tid; o < 32*NH; o += 256) {
            const int h = o >> 5, jj = o & 31;
            g_bpairT[(size_t)h*NNN + i*NTOK + j0 + jj] =
                0.5773502692f * (tr[jj][h] + bb[h]);
        }
    }
}

// ---------------- Kernel 4 (PROFILED SLOT): fused softmax + o_pair ----------
// grid 512 (per i), block 256.
__global__ void __launch_bounds__(256)
attn_opair(const float* __restrict__ z, const float* __restrict__ mask)
{
    __shared__ float a_s[NH][NTOK];      // 24 KB (logits -> attn in place)
    __shared__ float part[2][NH][128];   // 12 KB
    __shared__ float sinv[NH];
    const int i = blockIdx.x;
    const int tid = threadIdx.x;
    const int w = tid >> 5, l = tid & 31;

    // --- combined logits + mask ---
    const float mi = mask[i];
    for (int idx = tid; idx < NH*NTOK; idx += 256) {
        const int h = idx >> 9, j = idx & 511;
        const float mterm = 100000.0f * (mi*mask[j] - 1.0f);
        a_s[h][j] = g_qk[(size_t)h*NNN + i*NTOK + j]
                  + g_bpairT[(size_t)h*NNN + i*NTOK + j] + mterm;
    }
    __syncthreads();

    // --- softmax: warp w handles heads w, w+8 ---
    for (int h = w; h < NH; h += 8) {
        float m = -3.0e38f;
        #pragma unroll
        for (int t = 0; t < 16; t++)
            m = fmaxf(m, a_s[h][t*32 + l]);
        #pragma unroll
        for (int o = 16; o > 0; o >>= 1)
            m = fmaxf(m, __shfl_xor_sync(0xffffffffu, m, o));
        float su = 0.f;
        #pragma unroll
        for (int t = 0; t < 16; t++) {
            const float e = __expf(a_s[h][t*32 + l] - m);
            a_s[h][t*32 + l] = e;
            su += e;
        }
        #pragma unroll
        for (int o = 16; o > 0; o >>= 1)
            su += __shfl_xor_sync(0xffffffffu, su, o);
        if (l == 0) sinv[h] = 1.0f / su;
    }
    __syncthreads();

    // --- normalize in smem + write g_attn for ovh ---
    for (int idx = tid; idx < NH*NTOK; idx += 256) {
        const int h = idx >> 9, j = idx & 511;
        const float v = a_s[h][j] * sinv[h];
        a_s[h][j] = v;
        g_attn[(size_t)h*NNN + i*NTOK + j] = v;
    }
    __syncthreads();

    // --- o_pair = a @ z : warp w owns j in [w*64, w*64+64), lane l cols 4l..4l+3
    ull acc[NH][2];
    #pragma unroll
    for (int h = 0; h < NH; h++) { acc[h][0] = 0ULL; acc[h][1] = 0ULL; }

    const int jbase = w * 64;
    const double2* zq = (const double2*)(z + ((size_t)i*NTOK + jbase)*NCZ) + l;
    #pragma unroll 2
    for (int jj4 = 0; jj4 < 16; jj4++) {
        const double2 z0 = zq[(jj4*4 + 0)*32];
        const double2 z1 = zq[(jj4*4 + 1)*32];
        const double2 z2 = zq[(jj4*4 + 2)*32];
        const double2 z3 = zq[(jj4*4 + 3)*32];
        const ull z0a = LL(z0.x), z0b = LL(z0.y);
        const ull z1a = LL(z1.x), z1b = LL(z1.y);
        const ull z2a = LL(z2.x), z2b = LL(z2.y);
        const ull z3a = LL(z3.x), z3b = LL(z3.y);
        #pragma unroll
        for (int h = 0; h < NH; h++) {
            const float4 a4 = *(const float4*)&a_s[h][jbase + jj4*4];
            ull d;
            d = pk2(a4.x,a4.x); acc[h][0]=fmaf2(d,z0a,acc[h][0]); acc[h][1]=fmaf2(d,z0b,acc[h][1]);
            d = pk2(a4.y,a4.y); acc[h][0]=fmaf2(d,z1a,acc[h][0]); acc[h][1]=fmaf2(d,z1b,acc[h][1]);
            d = pk2(a4.z,a4.z); acc[h][0]=fmaf2(d,z2a,acc[h][0]); acc[h][1]=fmaf2(d,z2b,acc[h][1]);
            d = pk2(a4.w,a4.w); acc[h][0]=fmaf2(d,z3a,acc[h][0]); acc[h][1]=fmaf2(d,z3b,acc[h][1]);
        }
    }

    // --- phased reduce into part[2] ---
    if (w < 2) {
        #pragma unroll
        for (int h = 0; h < NH; h++)
            *(double2*)&part[w][h][l*4] = make_double2(DD(acc[h][0]), DD(acc[h][1]));
    }
    __syncthreads();
    if (w == 2 || w == 3) {
        #pragma unroll
        for (int h = 0; h < NH; h++) {
            ull* pp = (ull*)&part[w-2][h][l*4];
            pp[0] = addf2(pp[0], acc[h][0]);
            pp[1] = addf2(pp[1], acc[h][1]);
        }
    }
    __syncthreads();
    if (w == 4 || w == 5) {
        #pragma unroll
        for (int h = 0; h < NH; h++) {
            ull* pp = (ull*)&part[w-4][h][l*4];
            pp[0] = addf2(pp[0], acc[h][0]);
            pp[1] = addf2(pp[1], acc[h][1]);
        }
    }
    __syncthreads();
    if (w == 6 || w == 7) {
        #pragma unroll
        for (int h = 0; h < NH; h++) {
            ull* pp = (ull*)&part[w-6][h][l*4];
            pp[0] = addf2(pp[0], acc[h][0]);
            pp[1] = addf2(pp[1], acc[h][1]);
        }
    }
    __syncthreads();

    for (int o = tid; o < NH*128; o += 256) {
        const int h = o >> 7, c = o & 127;
        g_cat[i*NOUTD + 576 + o] = part[0][h][c] + part[1][h][c];
    }
}

// ---------------- Kernel 5a: o & o_pt GEMM, split-K 4, 64-row tiles ---------
__global__ void __launch_bounds__(256)
ovh_gemm(void)
{
    __shared__ float As[64][65];
    __shared__ float Vs[64][40];
    const int tid = threadIdx.x;
    const int i0 = blockIdx.x * 64;
    const int h  = blockIdx.y;
    const int ks = blockIdx.z;

    const int rr = tid & 31, g = tid >> 5;
    float acc0[5] = {0.f,0.f,0.f,0.f,0.f};
    float acc1[5] = {0.f,0.f,0.f,0.f,0.f};

    for (int k0 = ks*128; k0 < ks*128 + 128; k0 += 64) {
        for (int idx = tid; idx < 64*64; idx += 256) {
            const int row = idx >> 6, k = idx & 63;
            As[row][k] = g_attn[(size_t)(h*NTOK + i0+row)*NTOK + k0 + k];
        }
        for (int idx = tid; idx < 64*40; idx += 256) {
            const int k = idx / 40, c = idx % 40;
            Vs[k][c] = g_vcat[(h*NTOK + k0 + k)*40 + c];
        }
        __syncthreads();
        #pragma unroll 8
        for (int k = 0; k < 64; k++) {
            const float a0 = As[rr][k];
            const float a1 = As[rr+32][k];
            #pragma unroll
            for (int u = 0; u < 5; u++) {
                const float v = Vs[k][g*5 + u];
                acc0[u] += a0 * v;
                acc1[u] += a1 * v;
            }
        }
        __syncthreads();
    }
    float* dst = g_ovhp + ((size_t)ks*NH + h)*NTOK*40;
    #pragma unroll
    for (int u = 0; u < 5; u++) {
        dst[(i0+rr)   *40 + g*5 + u] = acc0[u];
        dst[(i0+rr+32)*40 + g*5 + u] = acc1[u];
    }
}

// ---------------- Kernel 5b: reduce split-K + rotation epilogue -------------
__global__ void __launch_bounds__(256)
ovh_reduce(const float* __restrict__ rot, const float* __restrict__ trans)
{
    __shared__ float Cs[32][40];
    const int tid = threadIdx.x;
    const int i0 = blockIdx.x * 32;
    const int h  = blockIdx.y;

    for (int idx = tid; idx < 32*40; idx += 256) {
        const int rr = idx / 40, c = idx % 40;
        float sv = 0.f;
        #pragma unroll
        for (int ks = 0; ks < 4; ks++)
            sv += g_ovhp[(((size_t)ks*NH + h)*NTOK + i0 + rr)*40 + c];
        Cs[rr][c] = sv;
    }
    __syncthreads();

    for (int idx = tid; idx < 32*16; idx += 256) {
        const int rr = idx >> 4, c = idx & 15;
        g_cat[(i0+rr)*NOUTD + h*16 + c] = Cs[rr][c];
    }
    for (int idx = tid; idx < 32*8; idx += 256) {
        const int rr = idx >> 3, p = idx & 7;
        const int i = i0 + rr;
        const float gx = Cs[rr][16 + p*3 + 0] - trans[i*3+0];
        const float gy = Cs[rr][16 + p*3 + 1] - trans[i*3+1];
        const float gz = Cs[rr][16 + p*3 + 2] - trans[i*3+2];
        const float* R = rot + i*9;
        const float lx = R[0]*gx + R[3]*gy + R[6]*gz;
        const float ly = R[1]*gx + R[4]*gy + R[7]*gz;
        const float lz = R[2]*gx + R[5]*gy + R[8]*gz;
        const int m = h*8 + p;
        g_cat[i*NOUTD + 192 + m] = lx;
        g_cat[i*NOUTD + 288 + m] = ly;
        g_cat[i*NOUTD + 384 + m] = lz;
        g_cat[i*NOUTD + 480 + m] = sqrtf(lx*lx + ly*ly + lz*lz + 1e-8f);
    }
}

// ---------------- Kernel 6: final GEMM, f32x2, 64x64 tiles, split-K 6 --------
__global__ void __launch_bounds__(256)
final_gemm(const float* __restrict__ Wout)
{
    __shared__ float AsT[32][68];
    __shared__ float Bs[32][68];
    const int bx = blockIdx.x, by = blockIdx.y, bz = blockIdx.z;
    const int tid = threadIdx.x;
    const int ty = tid >> 4, tx = tid & 15;
    const int kbeg = bz * 352;

    ull acc[4][2];
    #pragma unroll
    for (int rr = 0; rr < 4; rr++) { acc[rr][0] = 0ULL; acc[rr][1] = 0ULL; }

    for (int kt = kbeg; kt < kbeg + 352; kt += 32) {
        for (int idx = tid; idx < 2048; idx += 256) {
            const int r = idx >> 5, k = idx & 31;
            AsT[k][r] = g_cat[(by*64 + r)*NOUTD + kt + k];
        }
        for (int idx = tid; idx < 2048; idx += 256) {
            const int k = idx >> 6, c = idx & 63;
            Bs[k][c] = Wout[(kt + k)*NCS + bx*64 + c];
        }
        __syncthreads();
        #pragma unroll
        for (int k = 0; k < 32; k++) {
            const float4 a4 = *(const float4*)&AsT[k][ty*4];
            const double2 bd = *(const double2*)&Bs[k][tx*4];
            const ull b01 = LL(bd.x), b23 = LL(bd.y);
            ull d;
            d = pk2(a4.x,a4.x); acc[0][0]=fmaf2(d,b01,acc[0][0]); acc[0][1]=fmaf2(d,b23,acc[0][1]);
            d = pk2(a4.y,a4.y); acc[1][0]=fmaf2(d,b01,acc[1][0]); acc[1][1]=fmaf2(d,b23,acc[1][1]);
            d = pk2(a4.z,a4.z); acc[2][0]=fmaf2(d,b01,acc[2][0]); acc[2][1]=fmaf2(d,b23,acc[2][1]);
            d = pk2(a4.w,a4.w); acc[3][0]=fmaf2(d,b01,acc[3][0]); acc[3][1]=fmaf2(d,b23,acc[3][1]);
        }
        __syncthreads();
    }
    float* dst = g_fpart + (size_t)bz*NTOK*NCS;
    #pragma unroll
    for (int rr = 0; rr < 4; rr++) {
        double2 st = make_double2(DD(acc[rr][0]), DD(acc[rr][1]));
        *(double2*)&dst[(by*64 + ty*4 + rr)*NCS + bx*64 + tx*4] = st;
    }
}

__global__ void final_add(const float* __restrict__ bout, float* __restrict__ out)
{
    const int o = blockIdx.x*256 + threadIdx.x;
    if (o >= NTOK*NCS) return;
    float sv = bout[o % NCS];
    #pragma unroll
    for (int p = 0; p < 6; p++) sv += g_fpart[p*NTOK*NCS + o];
    out[o] = sv;
}

// ---------------- launch ------------------------------------------------------
extern "C" void kernel_launch(void* const* d_in, const int* in_sizes, int n_in,
                              void* d_out, int out_size)
{
    const float* s     = (const float*)d_in[0];
    const float* z     = (const float*)d_in[1];
    const float* rot   = (const float*)d_in[2];
    const float* trans = (const float*)d_in[3];
    const float* mask  = (const float*)d_in[4];
    const float* Wq    = (const float*)d_in[5];
    const float* bq    = (const float*)d_in[6];
    const float* Wkv   = (const float*)d_in[7];
    const float* bkv   = (const float*)d_in[8];
    const float* Wqp   = (const float*)d_in[9];
    const float* bqp   = (const float*)d_in[10];
    const float* Wkvp  = (const float*)d_in[11];
    const float* bkvp  = (const float*)d_in[12];
    const float* Wb    = (const float*)d_in[13];
    const float* bb    = (const float*)d_in[14];
    const float* hwts  = (const float*)d_in[15];
    const float* Wout  = (const float*)d_in[16];
    const float* bout  = (const float*)d_in[17];
    float* out = (float*)d_out;

    proj_kernel<<<dim3(16,19,1), 256>>>(s, Wq,bq, Wkv,bkv, Wqp,bqp, Wkvp,bkvp);
    prep_kernel<<<NTOK, 256>>>(rot, trans, hwts);
    qkbp_kernel<<<768 + 8192, 256>>>(z, Wb, bb);
    attn_opair<<<NTOK, 256>>>(z, mask);             // <- profiled slot (#4)
    ovh_gemm<<<dim3(8,12,4), 256>>>();
    ovh_reduce<<<dim3(16,12,1), 256>>>(rot, trans);
    final_gemm<<<dim3(6,8,6), 256>>>(Wout);
    final_add<<<(NTOK*NCS + 255)/256, 256>>>(bout, out);
}

// round 16
// speedup vs baseline: 1.0329x; 1.0329x over previous
#include <cuda_runtime.h>
#include <math.h>

#define NTOK 512
#define NH   12
#define NCH  16
#define NPQ  4
#define NPV  8
#define NCS  384
#define NCZ  128
#define NHC  192
#define NOUTD 2112
#define NNN  (NTOK*NTOK)

typedef unsigned long long ull;

// ---- f32x2 packed-FMA helpers (Blackwell) ----------------------------------
__device__ __forceinline__ ull pk2(float a, float b) {
    ull r;
    asm("mov.b64 %0, {%1,%2};" : "=l"(r)
        : "r"(__float_as_uint(a)), "r"(__float_as_uint(b)));
    return r;
}
__device__ __forceinline__ ull fmaf2(ull a, ull b, ull c) {
    ull d;
    asm("fma.rn.f32x2 %0, %1, %2, %3;" : "=l"(d) : "l"(a), "l"(b), "l"(c));
    return d;
}
__device__ __forceinline__ ull addf2(ull a, ull b) {
    ull d;
    asm("add.rn.f32x2 %0, %1, %2;" : "=l"(d) : "l"(a), "l"(b));
    return d;
}
__device__ __forceinline__ float2 upk2(ull a) {
    unsigned lo_, hi_;
    asm("mov.b64 {%0,%1}, %2;" : "=r"(lo_), "=r"(hi_) : "l"(a));
    return make_float2(__uint_as_float(lo_), __uint_as_float(hi_));
}
#define LL(x) __double_as_longlong(x)
#define DD(x) __longlong_as_double(x)

// ---------------- scratch ----------------------------------------------------
__device__ float g_qraw[NTOK*NHC];
__device__ float g_kvraw[NTOK*2*NHC];
__device__ float g_qpraw[NTOK*NH*NPQ*3];
__device__ float g_kvpraw[NTOK*NH*(NPQ+NPV)*3];
__device__ float g_qaug[NTOK*NH*32];
__device__ float g_kaugT[NH*32*NTOK];
__device__ float g_vcat[NH*NTOK*40];
__device__ float g_bpairT[NH*NNN];               // 0.577*(z@Wb+bb) [h][i][j]
__device__ float g_qk[NH*NNN];                   // [h][i][j]
__device__ float g_attn[NH*NNN];                 // [h][i][j]
__device__ float g_cat[NTOK*NOUTD];
__device__ float g_fpart[6*NTOK*NCS];
__device__ float g_ovhp[4*NH*NTOK*40];

// ---------------- Kernel 1: projections from s (f32x2, 32 tokens/blk) -------
__global__ void __launch_bounds__(256)
proj_kernel(const float* __restrict__ s,
            const float* __restrict__ Wq,   const float* __restrict__ bq,
            const float* __restrict__ Wkv,  const float* __restrict__ bkv,
            const float* __restrict__ Wqp,  const float* __restrict__ bqp,
            const float* __restrict__ Wkvp, const float* __restrict__ bkvp)
{
    __shared__ float s_s[32][384];
    const int tid = threadIdx.x;
    const int i0  = blockIdx.x * 32;
    for (int idx = tid; idx < 32*384; idx += 256)
        s_s[idx/384][idx%384] = s[i0*384 + idx];
    __syncthreads();

    const float* W; const float* bias; float* out; int Nc; int ct;
    const int by = blockIdx.y;
    if      (by < 3)  { W=Wq;   bias=bq;   out=g_qraw;   Nc=192; ct=by;    }
    else if (by < 9)  { W=Wkv;  bias=bkv;  out=g_kvraw;  Nc=384; ct=by-3;  }
    else if (by < 12) { W=Wqp;  bias=bqp;  out=g_qpraw;  Nc=144; ct=by-9;  }
    else              { W=Wkvp; bias=bkvp; out=g_kvpraw; Nc=432; ct=by-12; }

    const int col = ct*64 + (tid & 63);
    if (col >= Nc) return;
    const int t0 = (tid >> 6) * 8;

    ull a[8];
    #pragma unroll
    for (int rr = 0; rr < 8; rr++) a[rr] = 0ULL;

    #pragma unroll 2
    for (int k = 0; k < 384; k += 4) {
        const float w0 = W[(k+0)*Nc + col];
        const float w1 = W[(k+1)*Nc + col];
        const float w2 = W[(k+2)*Nc + col];
        const float w3 = W[(k+3)*Nc + col];
        const ull wp01 = pk2(w0,w1), wp23 = pk2(w2,w3);
        #pragma unroll
        for (int rr = 0; rr < 8; rr++) {
            const double2 v = *(const double2*)&s_s[t0+rr][k];
            a[rr] = fmaf2(LL(v.x), wp01, a[rr]);
            a[rr] = fmaf2(LL(v.y), wp23, a[rr]);
        }
    }
    const float bv = bias[col];
    #pragma unroll
    for (int rr = 0; rr < 8; rr++) {
        const float2 u = upk2(a[rr]);
        out[(i0+t0+rr)*Nc + col] = u.x + u.y + bv;
    }
}

// ---------------- Kernel 2: rotate points, build Q'/K'^T/Vcat ---------------
__global__ void prep_kernel(const float* __restrict__ rot, const float* __restrict__ trans,
                            const float* __restrict__ hwts)
{
    __shared__ float qpts_s[144];
    __shared__ float kpts_s[144];
    __shared__ float vpts_s[288];
    __shared__ float shw[NH];
    const int i = blockIdx.x;
    const int tid = threadIdx.x;

    if (tid < NH)
        shw[tid] = log1pf(__expf(hwts[tid])) * 0.1360827635f;

    if (tid < 192) {
        const int m = tid;
        const float* R = rot + i*9;
        const float tx = trans[i*3+0], ty = trans[i*3+1], tz = trans[i*3+2];
        float x, y, zc; float* dst;
        if (m < 48) {
            const float* src = g_qpraw + i*144;
            x = src[m]; y = src[48+m]; zc = src[96+m];
            dst = qpts_s + m*3;
        } else {
            const int mm = m - 48;
            const float* src = g_kvpraw + i*432;
            x = src[mm]; y = src[144+mm]; zc = src[288+mm];
            const int h = mm / 12, pp = mm % 12;
            if (pp < 4) dst = kpts_s + (h*4+pp)*3;
            else        dst = vpts_s + (h*8 + pp-4)*3;
        }
        dst[0] = R[0]*x + R[1]*y + R[2]*zc + tx;
        dst[1] = R[3]*x + R[4]*y + R[5]*zc + ty;
        dst[2] = R[6]*x + R[7]*y + R[8]*zc + tz;
    }
    __syncthreads();

    for (int idx = tid; idx < 384; idx += 256) {
        const int h = idx >> 5, d = idx & 31;
        const float hw = shw[h];
        float qv, kv;
        if (d < 16) {
            qv = 0.1443375673f * g_qraw[i*NHC + h*16 + d];
            kv = g_kvraw[i*384 + h*32 + d];
        } else if (d < 28) {
            qv = hw * qpts_s[h*12 + d-16];
            kv = kpts_s[h*12 + d-16];
        } else if (d == 28) {
            float qn = 0.f;
            #pragma unroll
            for (int e = 0; e < 12; e++) { const float t = qpts_s[h*12+e]; qn += t*t; }
            qv = -0.5f * hw * qn;
            kv = 1.0f;
        } else if (d == 29) {
            qv = 1.0f;
            float kn = 0.f;
            #pragma unroll
            for (int e = 0; e < 12; e++) { const float t = kpts_s[h*12+e]; kn += t*t; }
            kv = -0.5f * hw * kn;
        } else { qv = 0.f; kv = 0.f; }
        g_qaug[(i*NH + h)*32 + d] = qv;
        g_kaugT[(h*32 + d)*NTOK + i] = kv;
    }

    for (int idx = tid; idx < 480; idx += 256) {
        const int h = idx / 40, d = idx % 40;
        const float v = (d < 16) ? g_kvraw[i*384 + h*32 + 16 + d]
                                 : vpts_s[h*24 + d-16];
        g_vcat[(h*NTOK + i)*40 + d] = v;
    }
}

// ---------------- Kernel 3 (FAT): qk tiles + bpair slabs (round-12 body) ----
// blocks [0,768): qk 64x64 tiles; blocks [768, 768+4096): bpair 64-row slabs.
__global__ void __launch_bounds__(256)
qkbp_kernel(const float* __restrict__ z, const float* __restrict__ Wb,
            const float* __restrict__ bb)
{
    const int tid = threadIdx.x;

    if (blockIdx.x < 768) {
        // ---- qk tile ----
        __shared__ float QsT[32][68];
        __shared__ float Ks[32][68];
        const int bx = blockIdx.x;
        const int j0 = (bx & 7) * 64;
        const int i0 = ((bx >> 3) & 7) * 64;
        const int h  = bx >> 6;

        for (int idx = tid; idx < 2048; idx += 256) {
            const int r = idx >> 5, d = idx & 31;
            QsT[d][r] = g_qaug[((i0+r)*NH + h)*32 + d];
        }
        for (int idx = tid; idx < 2048; idx += 256) {
            const int d = idx >> 6, j = idx & 63;
            Ks[d][j] = g_kaugT[(h*32 + d)*NTOK + j0 + j];
        }
        __syncthreads();

        const int ty = tid >> 4, tx = tid & 15;
        ull acc[4][2];
        #pragma unroll
        for (int rr = 0; rr < 4; rr++) { acc[rr][0] = 0ULL; acc[rr][1] = 0ULL; }

        #pragma unroll
        for (int d = 0; d < 32; d++) {
            const double2 kd = *(const double2*)&Ks[d][tx*4];
            const ull k01 = LL(kd.x), k23 = LL(kd.y);
            const float4 qa = *(const float4*)&QsT[d][ty*4];
            ull dr;
            dr = pk2(qa.x,qa.x); acc[0][0]=fmaf2(dr,k01,acc[0][0]); acc[0][1]=fmaf2(dr,k23,acc[0][1]);
            dr = pk2(qa.y,qa.y); acc[1][0]=fmaf2(dr,k01,acc[1][0]); acc[1][1]=fmaf2(dr,k23,acc[1][1]);
            dr = pk2(qa.z,qa.z); acc[2][0]=fmaf2(dr,k01,acc[2][0]); acc[2][1]=fmaf2(dr,k23,acc[2][1]);
            dr = pk2(qa.w,qa.w); acc[3][0]=fmaf2(dr,k01,acc[3][0]); acc[3][1]=fmaf2(dr,k23,acc[3][1]);
        }
        #pragma unroll
        for (int rr = 0; rr < 4; rr++) {
            double2 st = make_double2(DD(acc[rr][0]), DD(acc[rr][1]));
            *(double2*)&g_qk[(size_t)(h*NTOK + i0 + ty*4+rr)*NTOK + j0 + tx*4] = st;
        }
    } else {
        // ---- bpair slab: round-8/12 measured-best body ----
        __shared__ float wbT[NH][128];
        __shared__ float tr[64][13];
        const int row0 = (blockIdx.x - 768) * 64;
        const int i  = row0 >> 9;
        const int j0 = row0 & 511;

        for (int idx = tid; idx < NH*128; idx += 256) {
            const int h = idx >> 7, c = idx & 127;
            wbT[h][c] = Wb[c*NH + h];
        }
        __syncthreads();

        const int q  = tid & 3;
        const int r  = (tid >> 2) & 31;
        const int h0 = (tid >> 7) * 6;

        const double2* zpa = (const double2*)z + (size_t)(row0 + r)*32;
        const double2* zpb = zpa + 32*32;

        double2 za[8], zb[8];
        #pragma unroll
        for (int it = 0; it < 8; it++) { za[it] = zpa[it*4 + q]; zb[it] = zpb[it*4 + q]; }

        ull acca[6], accb[6];
        #pragma unroll
        for (int hh = 0; hh < 6; hh++) { acca[hh] = 0ULL; accb[hh] = 0ULL; }

        #pragma unroll
        for (int it = 0; it < 8; it++) {
            const ull a01 = LL(za[it].x), a23 = LL(za[it].y);
            const ull b01 = LL(zb[it].x), b23 = LL(zb[it].y);
            const int cbase = (it*4 + q) * 4;
            #pragma unroll
            for (int hh = 0; hh < 6; hh++) {
                const double2 wd = *(const double2*)&wbT[h0+hh][cbase];
                const ull w01 = LL(wd.x), w23 = LL(wd.y);
                acca[hh] = fmaf2(a01, w01, acca[hh]);
                acca[hh] = fmaf2(a23, w23, acca[hh]);
                accb[hh] = fmaf2(b01, w01, accb[hh]);
                accb[hh] = fmaf2(b23, w23, accb[hh]);
            }
        }
        #pragma unroll
        for (int hh = 0; hh < 6; hh++) {
            const float2 ua = upk2(acca[hh]);
            float va = ua.x + ua.y;
            va += __shfl_xor_sync(0xffffffffu, va, 1);
            va += __shfl_xor_sync(0xffffffffu, va, 2);
            const float2 ub = upk2(accb[hh]);
            float vb = ub.x + ub.y;
            vb += __shfl_xor_sync(0xffffffffu, vb, 1);
            vb += __shfl_xor_sync(0xffffffffu, vb, 2);
            if (q == 0) {
                tr[r][h0+hh]      = va;
                tr[r+32][h0+hh]   = vb;
            }
        }
        __syncthreads();

        for (int o = tid; o < 64*NH; o += 256) {
            const int h = o >> 6, jj = o & 63;
            g_bpairT[(size_t)h*NNN + i*NTOK + j0 + jj] =
                0.5773502692f * (tr[jj][h] + bb[h]);
        }
    }
}

// ---------------- Kernel 4 (PROFILED SLOT): fused softmax + o_pair ----------
// grid 512 (per i), block 256.
__global__ void __launch_bounds__(256)
attn_opair(const float* __restrict__ z, const float* __restrict__ mask)
{
    __shared__ float a_s[NH][NTOK];      // 24 KB (logits -> attn in place)
    __shared__ float part[2][NH][128];   // 12 KB
    __shared__ float sinv[NH];
    const int i = blockIdx.x;
    const int tid = threadIdx.x;
    const int w = tid >> 5, l = tid & 31;

    // --- combined logits + mask ---
    const float mi = mask[i];
    for (int idx = tid; idx < NH*NTOK; idx += 256) {
        const int h = idx >> 9, j = idx & 511;
        const float mterm = 100000.0f * (mi*mask[j] - 1.0f);
        a_s[h][j] = g_qk[(size_t)h*NNN + i*NTOK + j]
                  + g_bpairT[(size_t)h*NNN + i*NTOK + j] + mterm;
    }
    __syncthreads();

    // --- softmax: warp w handles heads w, w+8 ---
    for (int h = w; h < NH; h += 8) {
        float m = -3.0e38f;
        #pragma unroll
        for (int t = 0; t < 16; t++)
            m = fmaxf(m, a_s[h][t*32 + l]);
        #pragma unroll
        for (int o = 16; o > 0; o >>= 1)
            m = fmaxf(m, __shfl_xor_sync(0xffffffffu, m, o));
        float su = 0.f;
        #pragma unroll
        for (int t = 0; t < 16; t++) {
            const float e = __expf(a_s[h][t*32 + l] - m);
            a_s[h][t*32 + l] = e;
            su += e;
        }
        #pragma unroll
        for (int o = 16; o > 0; o >>= 1)
            su += __shfl_xor_sync(0xffffffffu, su, o);
        if (l == 0) sinv[h] = 1.0f / su;
    }
    __syncthreads();

    // --- normalize in smem + write g_attn for ovh ---
    for (int idx = tid; idx < NH*NTOK; idx += 256) {
        const int h = idx >> 9, j = idx & 511;
        const float v = a_s[h][j] * sinv[h];
        a_s[h][j] = v;
        g_attn[(size_t)h*NNN + i*NTOK + j] = v;
    }
    __syncthreads();

    // --- o_pair = a @ z : warp w owns j in [w*64, w*64+64), lane l cols 4l..4l+3
    ull acc[NH][2];
    #pragma unroll
    for (int h = 0; h < NH; h++) { acc[h][0] = 0ULL; acc[h][1] = 0ULL; }

    const int jbase = w * 64;
    const double2* zq = (const double2*)(z + ((size_t)i*NTOK + jbase)*NCZ) + l;
    #pragma unroll 2
    for (int jj4 = 0; jj4 < 16; jj4++) {
        const double2 z0 = zq[(jj4*4 + 0)*32];
        const double2 z1 = zq[(jj4*4 + 1)*32];
        const double2 z2 = zq[(jj4*4 + 2)*32];
        const double2 z3 = zq[(jj4*4 + 3)*32];
        const ull z0a = LL(z0.x), z0b = LL(z0.y);
        const ull z1a = LL(z1.x), z1b = LL(z1.y);
        const ull z2a = LL(z2.x), z2b = LL(z2.y);
        const ull z3a = LL(z3.x), z3b = LL(z3.y);
        #pragma unroll
        for (int h = 0; h < NH; h++) {
            const float4 a4 = *(const float4*)&a_s[h][jbase + jj4*4];
            ull d;
            d = pk2(a4.x,a4.x); acc[h][0]=fmaf2(d,z0a,acc[h][0]); acc[h][1]=fmaf2(d,z0b,acc[h][1]);
            d = pk2(a4.y,a4.y); acc[h][0]=fmaf2(d,z1a,acc[h][0]); acc[h][1]=fmaf2(d,z1b,acc[h][1]);
            d = pk2(a4.z,a4.z); acc[h][0]=fmaf2(d,z2a,acc[h][0]); acc[h][1]=fmaf2(d,z2b,acc[h][1]);
            d = pk2(a4.w,a4.w); acc[h][0]=fmaf2(d,z3a,acc[h][0]); acc[h][1]=fmaf2(d,z3b,acc[h][1]);
        }
    }

    // --- phased reduce into part[2] ---
    if (w < 2) {
        #pragma unroll
        for (int h = 0; h < NH; h++)
            *(double2*)&part[w][h][l*4] = make_double2(DD(acc[h][0]), DD(acc[h][1]));
    }
    __syncthreads();
    if (w == 2 || w == 3) {
        #pragma unroll
        for (int h = 0; h < NH; h++) {
            ull* pp = (ull*)&part[w-2][h][l*4];
            pp[0] = addf2(pp[0], acc[h][0]);
            pp[1] = addf2(pp[1], acc[h][1]);
        }
    }
    __syncthreads();
    if (w == 4 || w == 5) {
        #pragma unroll
        for (int h = 0; h < NH; h++) {
            ull* pp = (ull*)&part[w-4][h][l*4];
            pp[0] = addf2(pp[0], acc[h][0]);
            pp[1] = addf2(pp[1], acc[h][1]);
        }
    }
    __syncthreads();
    if (w == 6 || w == 7) {
        #pragma unroll
        for (int h = 0; h < NH; h++) {
            ull* pp = (ull*)&part[w-6][h][l*4];
            pp[0] = addf2(pp[0], acc[h][0]);
            pp[1] = addf2(pp[1], acc[h][1]);
        }
    }
    __syncthreads();

    for (int o = tid; o < NH*128; o += 256) {
        const int h = o >> 7, c = o & 127;
        g_cat[i*NOUTD + 576 + o] = part[0][h][c] + part[1][h][c];
    }
}

// ---------------- Kernel 5a: o & o_pt GEMM, split-K 4, 64-row tiles ---------
__global__ void __launch_bounds__(256)
ovh_gemm(void)
{
    __shared__ float As[64][65];
    __shared__ float Vs[64][40];
    const int tid = threadIdx.x;
    const int i0 = blockIdx.x * 64;
    const int h  = blockIdx.y;
    const int ks = blockIdx.z;

    const int rr = tid & 31, g = tid >> 5;
    float acc0[5] = {0.f,0.f,0.f,0.f,0.f};
    float acc1[5] = {0.f,0.f,0.f,0.f,0.f};

    for (int k0 = ks*128; k0 < ks*128 + 128; k0 += 64) {
        for (int idx = tid; idx < 64*64; idx += 256) {
            const int row = idx >> 6, k = idx & 63;
            As[row][k] = g_attn[(size_t)(h*NTOK + i0+row)*NTOK + k0 + k];
        }
        for (int idx = tid; idx < 64*40; idx += 256) {
            const int k = idx / 40, c = idx % 40;
            Vs[k][c] = g_vcat[(h*NTOK + k0 + k)*40 + c];
        }
        __syncthreads();
        #pragma unroll 8
        for (int k = 0; k < 64; k++) {
            const float a0 = As[rr][k];
            const float a1 = As[rr+32][k];
            #pragma unroll
            for (int u = 0; u < 5; u++) {
                const float v = Vs[k][g*5 + u];
                acc0[u] += a0 * v;
                acc1[u] += a1 * v;
            }
        }
        __syncthreads();
    }
    float* dst = g_ovhp + ((size_t)ks*NH + h)*NTOK*40;
    #pragma unroll
    for (int u = 0; u < 5; u++) {
        dst[(i0+rr)   *40 + g*5 + u] = acc0[u];
        dst[(i0+rr+32)*40 + g*5 + u] = acc1[u];
    }
}

// ---------------- Kernel 5b: reduce split-K + rotation epilogue -------------
__global__ void __launch_bounds__(256)
ovh_reduce(const float* __restrict__ rot, const float* __restrict__ trans)
{
    __shared__ float Cs[32][40];
    const int tid = threadIdx.x;
    const int i0 = blockIdx.x * 32;
    const int h  = blockIdx.y;

    for (int idx = tid; idx < 32*40; idx += 256) {
        const int rr = idx / 40, c = idx % 40;
        float sv = 0.f;
        #pragma unroll
        for (int ks = 0; ks < 4; ks++)
            sv += g_ovhp[(((size_t)ks*NH + h)*NTOK + i0 + rr)*40 + c];
        Cs[rr][c] = sv;
    }
    __syncthreads();

    for (int idx = tid; idx < 32*16; idx += 256) {
        const int rr = idx >> 4, c = idx & 15;
        g_cat[(i0+rr)*NOUTD + h*16 + c] = Cs[rr][c];
    }
    for (int idx = tid; idx < 32*8; idx += 256) {
        const int rr = idx >> 3, p = idx & 7;
        const int i = i0 + rr;
        const float gx = Cs[rr][16 + p*3 + 0] - trans[i*3+0];
        const float gy = Cs[rr][16 + p*3 + 1] - trans[i*3+1];
        const float gz = Cs[rr][16 + p*3 + 2] - trans[i*3+2];
        const float* R = rot + i*9;
        const float lx = R[0]*gx + R[3]*gy + R[6]*gz;
        const float ly = R[1]*gx + R[4]*gy + R[7]*gz;
        const float lz = R[2]*gx + R[5]*gy + R[8]*gz;
        const int m = h*8 + p;
        g_cat[i*NOUTD + 192 + m] = lx;
        g_cat[i*NOUTD + 288 + m] = ly;
        g_cat[i*NOUTD + 384 + m] = lz;
        g_cat[i*NOUTD + 480 + m] = sqrtf(lx*lx + ly*ly + lz*lz + 1e-8f);
    }
}

// ---------------- Kernel 6: final GEMM, f32x2, 64x64 tiles, split-K 6 --------
__global__ void __launch_bounds__(256)
final_gemm(const float* __restrict__ Wout)
{
    __shared__ float AsT[32][68];
    __shared__ float Bs[32][68];
    const int bx = blockIdx.x, by = blockIdx.y, bz = blockIdx.z;
    const int tid = threadIdx.x;
    const int ty = tid >> 4, tx = tid & 15;
    const int kbeg = bz * 352;

    ull acc[4][2];
    #pragma unroll
    for (int rr = 0; rr < 4; rr++) { acc[rr][0] = 0ULL; acc[rr][1] = 0ULL; }

    for (int kt = kbeg; kt < kbeg + 352; kt += 32) {
        for (int idx = tid; idx < 2048; idx += 256) {
            const int r = idx >> 5, k = idx & 31;
            AsT[k][r] = g_cat[(by*64 + r)*NOUTD + kt + k];
        }
        for (int idx = tid; idx < 2048; idx += 256) {
            const int k = idx >> 6, c = idx & 63;
            Bs[k][c] = Wout[(kt + k)*NCS + bx*64 + c];
        }
        __syncthreads();
        #pragma unroll
        for (int k = 0; k < 32; k++) {
            const float4 a4 = *(const float4*)&AsT[k][ty*4];
            const double2 bd = *(const double2*)&Bs[k][tx*4];
            const ull b01 = LL(bd.x), b23 = LL(bd.y);
            ull d;
            d = pk2(a4.x,a4.x); acc[0][0]=fmaf2(d,b01,acc[0][0]); acc[0][1]=fmaf2(d,b23,acc[0][1]);
            d = pk2(a4.y,a4.y); acc[1][0]=fmaf2(d,b01,acc[1][0]); acc[1][1]=fmaf2(d,b23,acc[1][1]);
            d = pk2(a4.z,a4.z); acc[2][0]=fmaf2(d,b01,acc[2][0]); acc[2][1]=fmaf2(d,b23,acc[2][1]);
            d = pk2(a4.w,a4.w); acc[3][0]=fmaf2(d,b01,acc[3][0]); acc[3][1]=fmaf2(d,b23,acc[3][1]);
        }
        __syncthreads();
    }
    float* dst = g_fpart + (size_t)bz*NTOK*NCS;
    #pragma unroll
    for (int rr = 0; rr < 4; rr++) {
        double2 st = make_double2(DD(acc[rr][0]), DD(acc[rr][1]));
        *(double2*)&dst[(by*64 + ty*4 + rr)*NCS + bx*64 + tx*4] = st;
    }
}

__global__ void final_add(const float* __restrict__ bout, float* __restrict__ out)
{
    const int o = blockIdx.x*256 + threadIdx.x;
    if (o >= NTOK*NCS) return;
    float sv = bout[o % NCS];
    #pragma unroll
    for (int p = 0; p < 6; p++) sv += g_fpart[p*NTOK*NCS + o];
    out[o] = sv;
}

// ---------------- launch ------------------------------------------------------
extern "C" void kernel_launch(void* const* d_in, const int* in_sizes, int n_in,
                              void* d_out, int out_size)
{
    const float* s     = (const float*)d_in[0];
    const float* z     = (const float*)d_in[1];
    const float* rot   = (const float*)d_in[2];
    const float* trans = (const float*)d_in[3];
    const float* mask  = (const float*)d_in[4];
    const float* Wq    = (const float*)d_in[5];
    const float* bq    = (const float*)d_in[6];
    const float* Wkv   = (const float*)d_in[7];
    const float* bkv   = (const float*)d_in[8];
    const float* Wqp   = (const float*)d_in[9];
    const float* bqp   = (const float*)d_in[10];
    const float* Wkvp  = (const float*)d_in[11];
    const float* bkvp  = (const float*)d_in[12];
    const float* Wb    = (const float*)d_in[13];
    const float* bb    = (const float*)d_in[14];
    const float* hwts  = (const float*)d_in[15];
    const float* Wout  = (const float*)d_in[16];
    const float* bout  = (const float*)d_in[17];
    float* out = (float*)d_out;

    proj_kernel<<<dim3(16,19,1), 256>>>(s, Wq,bq, Wkv,bkv, Wqp,bqp, Wkvp,bkvp);
    prep_kernel<<<NTOK, 256>>>(rot, trans, hwts);
    qkbp_kernel<<<768 + 4096, 256>>>(z, Wb, bb);
    attn_opair<<<NTOK, 256>>>(z, mask);             // <- profiled slot (#4)
    ovh_gemm<<<dim3(8,12,4), 256>>>();
    ovh_reduce<<<dim3(16,12,1), 256>>>(rot, trans);
    final_gemm<<<dim3(6,8,6), 256>>>(Wout);
    final_add<<<(NTOK*NCS + 255)/256, 256>>>(bout, out);
}

// round 17
// speedup vs baseline: 1.1008x; 1.0658x over previous
#include <cuda_runtime.h>
#include <math.h>

#define NTOK 512
#define NH   12
#define NCH  16
#define NPQ  4
#define NPV  8
#define NCS  384
#define NCZ  128
#define NHC  192
#define NOUTD 2112
#define NNN  (NTOK*NTOK)

typedef unsigned long long ull;

// ---- f32x2 packed-FMA helpers (Blackwell) ----------------------------------
__device__ __forceinline__ ull pk2(float a, float b) {
    ull r;
    asm("mov.b64 %0, {%1,%2};" : "=l"(r)
        : "r"(__float_as_uint(a)), "r"(__float_as_uint(b)));
    return r;
}
__device__ __forceinline__ ull fmaf2(ull a, ull b, ull c) {
    ull d;
    asm("fma.rn.f32x2 %0, %1, %2, %3;" : "=l"(d) : "l"(a), "l"(b), "l"(c));
    return d;
}
__device__ __forceinline__ ull addf2(ull a, ull b) {
    ull d;
    asm("add.rn.f32x2 %0, %1, %2;" : "=l"(d) : "l"(a), "l"(b));
    return d;
}
__device__ __forceinline__ float2 upk2(ull a) {
    unsigned lo_, hi_;
    asm("mov.b64 {%0,%1}, %2;" : "=r"(lo_), "=r"(hi_) : "l"(a));
    return make_float2(__uint_as_float(lo_), __uint_as_float(hi_));
}
#define LL(x) __double_as_longlong(x)
#define DD(x) __longlong_as_double(x)

// ---------------- scratch ----------------------------------------------------
__device__ float g_qraw[NTOK*NHC];
__device__ float g_kvraw[NTOK*2*NHC];
__device__ float g_qpraw[NTOK*NH*NPQ*3];
__device__ float g_kvpraw[NTOK*NH*(NPQ+NPV)*3];
__device__ float g_qaug[NTOK*NH*32];
__device__ float g_kaugT[NH*32*NTOK];
__device__ float g_vcat[NH*NTOK*40];
__device__ float g_bpairT[NH*NNN];               // 0.577*(z@Wb+bb) [h][i][j]
__device__ float g_qk[NH*NNN];                   // [h][i][j]
__device__ float g_attn[NH*NNN];                 // [h][i][j]
__device__ float g_cat[NTOK*NOUTD];
__device__ float g_fpart[6*NTOK*NCS];
__device__ float g_ovhp[4*NH*NTOK*40];

// ---------------- Kernel 1: projections from s (f32x2, 32 tokens/blk) -------
__global__ void __launch_bounds__(256)
proj_kernel(const float* __restrict__ s,
            const float* __restrict__ Wq,   const float* __restrict__ bq,
            const float* __restrict__ Wkv,  const float* __restrict__ bkv,
            const float* __restrict__ Wqp,  const float* __restrict__ bqp,
            const float* __restrict__ Wkvp, const float* __restrict__ bkvp)
{
    __shared__ float s_s[32][384];
    const int tid = threadIdx.x;
    const int i0  = blockIdx.x * 32;
    for (int idx = tid; idx < 32*384; idx += 256)
        s_s[idx/384][idx%384] = s[i0*384 + idx];
    __syncthreads();

    const float* W; const float* bias; float* out; int Nc; int ct;
    const int by = blockIdx.y;
    if      (by < 3)  { W=Wq;   bias=bq;   out=g_qraw;   Nc=192; ct=by;    }
    else if (by < 9)  { W=Wkv;  bias=bkv;  out=g_kvraw;  Nc=384; ct=by-3;  }
    else if (by < 12) { W=Wqp;  bias=bqp;  out=g_qpraw;  Nc=144; ct=by-9;  }
    else              { W=Wkvp; bias=bkvp; out=g_kvpraw; Nc=432; ct=by-12; }

    const int col = ct*64 + (tid & 63);
    if (col >= Nc) return;
    const int t0 = (tid >> 6) * 8;

    ull a[8];
    #pragma unroll
    for (int rr = 0; rr < 8; rr++) a[rr] = 0ULL;

    #pragma unroll 2
    for (int k = 0; k < 384; k += 4) {
        const float w0 = W[(k+0)*Nc + col];
        const float w1 = W[(k+1)*Nc + col];
        const float w2 = W[(k+2)*Nc + col];
        const float w3 = W[(k+3)*Nc + col];
        const ull wp01 = pk2(w0,w1), wp23 = pk2(w2,w3);
        #pragma unroll
        for (int rr = 0; rr < 8; rr++) {
            const double2 v = *(const double2*)&s_s[t0+rr][k];
            a[rr] = fmaf2(LL(v.x), wp01, a[rr]);
            a[rr] = fmaf2(LL(v.y), wp23, a[rr]);
        }
    }
    const float bv = bias[col];
    #pragma unroll
    for (int rr = 0; rr < 8; rr++) {
        const float2 u = upk2(a[rr]);
        out[(i0+t0+rr)*Nc + col] = u.x + u.y + bv;
    }
}

// ---------------- Kernel 2: rotate points, build Q'/K'^T/Vcat ---------------
__global__ void prep_kernel(const float* __restrict__ rot, const float* __restrict__ trans,
                            const float* __restrict__ hwts)
{
    __shared__ float qpts_s[144];
    __shared__ float kpts_s[144];
    __shared__ float vpts_s[288];
    __shared__ float shw[NH];
    const int i = blockIdx.x;
    const int tid = threadIdx.x;

    if (tid < NH)
        shw[tid] = log1pf(__expf(hwts[tid])) * 0.1360827635f;

    if (tid < 192) {
        const int m = tid;
        const float* R = rot + i*9;
        const float tx = trans[i*3+0], ty = trans[i*3+1], tz = trans[i*3+2];
        float x, y, zc; float* dst;
        if (m < 48) {
            const float* src = g_qpraw + i*144;
            x = src[m]; y = src[48+m]; zc = src[96+m];
            dst = qpts_s + m*3;
        } else {
            const int mm = m - 48;
            const float* src = g_kvpraw + i*432;
            x = src[mm]; y = src[144+mm]; zc = src[288+mm];
            const int h = mm / 12, pp = mm % 12;
            if (pp < 4) dst = kpts_s + (h*4+pp)*3;
            else        dst = vpts_s + (h*8 + pp-4)*3;
        }
        dst[0] = R[0]*x + R[1]*y + R[2]*zc + tx;
        dst[1] = R[3]*x + R[4]*y + R[5]*zc + ty;
        dst[2] = R[6]*x + R[7]*y + R[8]*zc + tz;
    }
    __syncthreads();

    for (int idx = tid; idx < 384; idx += 256) {
        const int h = idx >> 5, d = idx & 31;
        const float hw = shw[h];
        float qv, kv;
        if (d < 16) {
            qv = 0.1443375673f * g_qraw[i*NHC + h*16 + d];
            kv = g_kvraw[i*384 + h*32 + d];
        } else if (d < 28) {
            qv = hw * qpts_s[h*12 + d-16];
            kv = kpts_s[h*12 + d-16];
        } else if (d == 28) {
            float qn = 0.f;
            #pragma unroll
            for (int e = 0; e < 12; e++) { const float t = qpts_s[h*12+e]; qn += t*t; }
            qv = -0.5f * hw * qn;
            kv = 1.0f;
        } else if (d == 29) {
            qv = 1.0f;
            float kn = 0.f;
            #pragma unroll
            for (int e = 0; e < 12; e++) { const float t = kpts_s[h*12+e]; kn += t*t; }
            kv = -0.5f * hw * kn;
        } else { qv = 0.f; kv = 0.f; }
        g_qaug[(i*NH + h)*32 + d] = qv;
        g_kaugT[(h*32 + d)*NTOK + i] = kv;
    }

    for (int idx = tid; idx < 480; idx += 256) {
        const int h = idx / 40, d = idx % 40;
        const float v = (d < 16) ? g_kvraw[i*384 + h*32 + 16 + d]
                                 : vpts_s[h*24 + d-16];
        g_vcat[(h*NTOK + i)*40 + d] = v;
    }
}

// ---------------- Kernel 3 (FAT): qk tiles + bpair slabs (round-12 body) ----
__global__ void __launch_bounds__(256)
qkbp_kernel(const float* __restrict__ z, const float* __restrict__ Wb,
            const float* __restrict__ bb)
{
    const int tid = threadIdx.x;

    if (blockIdx.x < 768) {
        // ---- qk tile ----
        __shared__ float QsT[32][68];
        __shared__ float Ks[32][68];
        const int bx = blockIdx.x;
        const int j0 = (bx & 7) * 64;
        const int i0 = ((bx >> 3) & 7) * 64;
        const int h  = bx >> 6;

        for (int idx = tid; idx < 2048; idx += 256) {
            const int r = idx >> 5, d = idx & 31;
            QsT[d][r] = g_qaug[((i0+r)*NH + h)*32 + d];
        }
        for (int idx = tid; idx < 2048; idx += 256) {
            const int d = idx >> 6, j = idx & 63;
            Ks[d][j] = g_kaugT[(h*32 + d)*NTOK + j0 + j];
        }
        __syncthreads();

        const int ty = tid >> 4, tx = tid & 15;
        ull acc[4][2];
        #pragma unroll
        for (int rr = 0; rr < 4; rr++) { acc[rr][0] = 0ULL; acc[rr][1] = 0ULL; }

        #pragma unroll
        for (int d = 0; d < 32; d++) {
            const double2 kd = *(const double2*)&Ks[d][tx*4];
            const ull k01 = LL(kd.x), k23 = LL(kd.y);
            const float4 qa = *(const float4*)&QsT[d][ty*4];
            ull dr;
            dr = pk2(qa.x,qa.x); acc[0][0]=fmaf2(dr,k01,acc[0][0]); acc[0][1]=fmaf2(dr,k23,acc[0][1]);
            dr = pk2(qa.y,qa.y); acc[1][0]=fmaf2(dr,k01,acc[1][0]); acc[1][1]=fmaf2(dr,k23,acc[1][1]);
            dr = pk2(qa.z,qa.z); acc[2][0]=fmaf2(dr,k01,acc[2][0]); acc[2][1]=fmaf2(dr,k23,acc[2][1]);
            dr = pk2(qa.w,qa.w); acc[3][0]=fmaf2(dr,k01,acc[3][0]); acc[3][1]=fmaf2(dr,k23,acc[3][1]);
        }
        #pragma unroll
        for (int rr = 0; rr < 4; rr++) {
            double2 st = make_double2(DD(acc[rr][0]), DD(acc[rr][1]));
            *(double2*)&g_qk[(size_t)(h*NTOK + i0 + ty*4+rr)*NTOK + j0 + tx*4] = st;
        }
    } else {
        // ---- bpair slab: round-8/12 measured-best body ----
        __shared__ float wbT[NH][128];
        __shared__ float tr[64][13];
        const int row0 = (blockIdx.x - 768) * 64;
        const int i  = row0 >> 9;
        const int j0 = row0 & 511;

        for (int idx = tid; idx < NH*128; idx += 256) {
            const int h = idx >> 7, c = idx & 127;
            wbT[h][c] = Wb[c*NH + h];
        }
        __syncthreads();

        const int q  = tid & 3;
        const int r  = (tid >> 2) & 31;
        const int h0 = (tid >> 7) * 6;

        const double2* zpa = (const double2*)z + (size_t)(row0 + r)*32;
        const double2* zpb = zpa + 32*32;

        double2 za[8], zb[8];
        #pragma unroll
        for (int it = 0; it < 8; it++) { za[it] = zpa[it*4 + q]; zb[it] = zpb[it*4 + q]; }

        ull acca[6], accb[6];
        #pragma unroll
        for (int hh = 0; hh < 6; hh++) { acca[hh] = 0ULL; accb[hh] = 0ULL; }

        #pragma unroll
        for (int it = 0; it < 8; it++) {
            const ull a01 = LL(za[it].x), a23 = LL(za[it].y);
            const ull b01 = LL(zb[it].x), b23 = LL(zb[it].y);
            const int cbase = (it*4 + q) * 4;
            #pragma unroll
            for (int hh = 0; hh < 6; hh++) {
                const double2 wd = *(const double2*)&wbT[h0+hh][cbase];
                const ull w01 = LL(wd.x), w23 = LL(wd.y);
                acca[hh] = fmaf2(a01, w01, acca[hh]);
                acca[hh] = fmaf2(a23, w23, acca[hh]);
                accb[hh] = fmaf2(b01, w01, accb[hh]);
                accb[hh] = fmaf2(b23, w23, accb[hh]);
            }
        }
        #pragma unroll
        for (int hh = 0; hh < 6; hh++) {
            const float2 ua = upk2(acca[hh]);
            float va = ua.x + ua.y;
            va += __shfl_xor_sync(0xffffffffu, va, 1);
            va += __shfl_xor_sync(0xffffffffu, va, 2);
            const float2 ub = upk2(accb[hh]);
            float vb = ub.x + ub.y;
            vb += __shfl_xor_sync(0xffffffffu, vb, 1);
            vb += __shfl_xor_sync(0xffffffffu, vb, 2);
            if (q == 0) {
                tr[r][h0+hh]      = va;
                tr[r+32][h0+hh]   = vb;
            }
        }
        __syncthreads();

        for (int o = tid; o < 64*NH; o += 256) {
            const int h = o >> 6, jj = o & 63;
            g_bpairT[(size_t)h*NNN + i*NTOK + j0 + jj] =
                0.5773502692f * (tr[jj][h] + bb[h]);
        }
    }
}

// ---------------- Kernel 4 (PROFILED SLOT): softmax -------------------------
__global__ void softmax_kernel(const float* __restrict__ mask)
{
    __shared__ float lgm[NH][NTOK];
    __shared__ float sinv[NH];
    const int i = blockIdx.x;
    const int j = threadIdx.x;

    const float mterm = 100000.0f * (mask[i]*mask[j] - 1.0f);
    #pragma unroll
    for (int h = 0; h < NH; h++)
        lgm[h][j] = g_qk[(size_t)h*NNN + i*NTOK + j]
                  + g_bpairT[(size_t)h*NNN + i*NTOK + j] + mterm;
    __syncthreads();

    const int lane = j & 31, wrp = j >> 5;
    if (wrp < NH) {
        float m = -3.0e38f;
        #pragma unroll
        for (int t = 0; t < 16; t++)
            m = fmaxf(m, lgm[wrp][t*32 + lane]);
        #pragma unroll
        for (int o = 16; o > 0; o >>= 1)
            m = fmaxf(m, __shfl_xor_sync(0xffffffffu, m, o));
        float su = 0.f;
        #pragma unroll
        for (int t = 0; t < 16; t++) {
            const float e = __expf(lgm[wrp][t*32 + lane] - m);
            lgm[wrp][t*32 + lane] = e;
            su += e;
        }
        #pragma unroll
        for (int o = 16; o > 0; o >>= 1)
            su += __shfl_xor_sync(0xffffffffu, su, o);
        if (lane == 0) sinv[wrp] = 1.0f / su;
    }
    __syncthreads();

    #pragma unroll
    for (int h = 0; h < NH; h++)
        g_attn[(size_t)h*NNN + i*NTOK + j] = lgm[h][j] * sinv[h];
}

// ---------------- Kernel 5 (FAT): opair blocks + ovh blocks ------------------
// blocks [0,512): opair per-i; blocks [512, 512+384): ovh 64-row tiles.
__global__ void __launch_bounds__(256)
opair_ovh(const float* __restrict__ z)
{
    __shared__ float shm[12288];   // 48 KB, aliased per branch
    const int tid = threadIdx.x;

    if (blockIdx.x < 512) {
        // ---- opair (round-14 body) ----
        float (*a_s)[NTOK]  = (float(*)[NTOK])shm;          // [12][512]
        float (*part)[NH][128] = (float(*)[NH][128])(shm + 6144); // [4][12][128]
        const int i = blockIdx.x;
        const int w = tid >> 5, l = tid & 31;
        const int jbase = w * 64;

        for (int idx = tid; idx < NH*NTOK; idx += 256)
            a_s[idx >> 9][idx & 511] = g_attn[(size_t)(idx >> 9)*NNN + i*NTOK + (idx & 511)];
        __syncthreads();

        ull acc[NH][2];
        #pragma unroll
        for (int h = 0; h < NH; h++) { acc[h][0] = 0ULL; acc[h][1] = 0ULL; }

        const double2* zq = (const double2*)(z + ((size_t)i*NTOK + jbase)*NCZ) + l;
        #pragma unroll 2
        for (int jj4 = 0; jj4 < 16; jj4++) {
            const double2 z0 = zq[(jj4*4 + 0)*32];
            const double2 z1 = zq[(jj4*4 + 1)*32];
            const double2 z2 = zq[(jj4*4 + 2)*32];
            const double2 z3 = zq[(jj4*4 + 3)*32];
            const ull z0a = LL(z0.x), z0b = LL(z0.y);
            const ull z1a = LL(z1.x), z1b = LL(z1.y);
            const ull z2a = LL(z2.x), z2b = LL(z2.y);
            const ull z3a = LL(z3.x), z3b = LL(z3.y);
            #pragma unroll
            for (int h = 0; h < NH; h++) {
                const float4 a4 = *(const float4*)&a_s[h][jbase + jj4*4];
                ull d;
                d = pk2(a4.x,a4.x); acc[h][0]=fmaf2(d,z0a,acc[h][0]); acc[h][1]=fmaf2(d,z0b,acc[h][1]);
                d = pk2(a4.y,a4.y); acc[h][0]=fmaf2(d,z1a,acc[h][0]); acc[h][1]=fmaf2(d,z1b,acc[h][1]);
                d = pk2(a4.z,a4.z); acc[h][0]=fmaf2(d,z2a,acc[h][0]); acc[h][1]=fmaf2(d,z2b,acc[h][1]);
                d = pk2(a4.w,a4.w); acc[h][0]=fmaf2(d,z3a,acc[h][0]); acc[h][1]=fmaf2(d,z3b,acc[h][1]);
            }
        }

        if (w < 4) {
            #pragma unroll
            for (int h = 0; h < NH; h++)
                *(double2*)&part[w][h][l*4] = make_double2(DD(acc[h][0]), DD(acc[h][1]));
        }
        __syncthreads();
        if (w >= 4) {
            #pragma unroll
            for (int h = 0; h < NH; h++) {
                ull* pp = (ull*)&part[w-4][h][l*4];
                pp[0] = addf2(pp[0], acc[h][0]);
                pp[1] = addf2(pp[1], acc[h][1]);
            }
        }
        __syncthreads();

        for (int o = tid; o < NH*128; o += 256) {
            const int h = o >> 7, c = o & 127;
            g_cat[i*NOUTD + 576 + o] =
                part[0][h][c] + part[1][h][c] + part[2][h][c] + part[3][h][c];
        }
    } else {
        // ---- ovh 64-row tile, split-K 4 (round-14 body) ----
        float (*As)[65] = (float(*)[65])shm;           // [64][65] = 4160
        float (*Vs)[40] = (float(*)[40])(shm + 4160);  // [64][40] = 2560
        const int bx2 = blockIdx.x - 512;
        const int i0 = (bx2 & 7) * 64;
        const int h  = (bx2 >> 3) % 12;
        const int ks = bx2 / 96;

        const int rr = tid & 31, g = tid >> 5;
        float acc0[5] = {0.f,0.f,0.f,0.f,0.f};
        float acc1[5] = {0.f,0.f,0.f,0.f,0.f};

        for (int k0 = ks*128; k0 < ks*128 + 128; k0 += 64) {
            for (int idx = tid; idx < 64*64; idx += 256) {
                const int row = idx >> 6, k = idx & 63;
                As[row][k] = g_attn[(size_t)(h*NTOK + i0+row)*NTOK + k0 + k];
            }
            for (int idx = tid; idx < 64*40; idx += 256) {
                const int k = idx / 40, c = idx % 40;
                Vs[k][c] = g_vcat[(h*NTOK + k0 + k)*40 + c];
            }
            __syncthreads();
            #pragma unroll 8
            for (int k = 0; k < 64; k++) {
                const float a0 = As[rr][k];
                const float a1 = As[rr+32][k];
                #pragma unroll
                for (int u = 0; u < 5; u++) {
                    const float v = Vs[k][g*5 + u];
                    acc0[u] += a0 * v;
                    acc1[u] += a1 * v;
                }
            }
            __syncthreads();
        }
        float* dst = g_ovhp + ((size_t)ks*NH + h)*NTOK*40;
        #pragma unroll
        for (int u = 0; u < 5; u++) {
            dst[(i0+rr)   *40 + g*5 + u] = acc0[u];
            dst[(i0+rr+32)*40 + g*5 + u] = acc1[u];
        }
    }
}

// ---------------- Kernel 6: reduce split-K + rotation epilogue --------------
__global__ void __launch_bounds__(256)
ovh_reduce(const float* __restrict__ rot, const float* __restrict__ trans)
{
    __shared__ float Cs[32][40];
    const int tid = threadIdx.x;
    const int i0 = blockIdx.x * 32;
    const int h  = blockIdx.y;

    for (int idx = tid; idx < 32*40; idx += 256) {
        const int rr = idx / 40, c = idx % 40;
        float sv = 0.f;
        #pragma unroll
        for (int ks = 0; ks < 4; ks++)
            sv += g_ovhp[(((size_t)ks*NH + h)*NTOK + i0 + rr)*40 + c];
        Cs[rr][c] = sv;
    }
    __syncthreads();

    for (int idx = tid; idx < 32*16; idx += 256) {
        const int rr = idx >> 4, c = idx & 15;
        g_cat[(i0+rr)*NOUTD + h*16 + c] = Cs[rr][c];
    }
    for (int idx = tid; idx < 32*8; idx += 256) {
        const int rr = idx >> 3, p = idx & 7;
        const int i = i0 + rr;
        const float gx = Cs[rr][16 + p*3 + 0] - trans[i*3+0];
        const float gy = Cs[rr][16 + p*3 + 1] - trans[i*3+1];
        const float gz = Cs[rr][16 + p*3 + 2] - trans[i*3+2];
        const float* R = rot + i*9;
        const float lx = R[0]*gx + R[3]*gy + R[6]*gz;
        const float ly = R[1]*gx + R[4]*gy + R[7]*gz;
        const float lz = R[2]*gx + R[5]*gy + R[8]*gz;
        const int m = h*8 + p;
        g_cat[i*NOUTD + 192 + m] = lx;
        g_cat[i*NOUTD + 288 + m] = ly;
        g_cat[i*NOUTD + 384 + m] = lz;
        g_cat[i*NOUTD + 480 + m] = sqrtf(lx*lx + ly*ly + lz*lz + 1e-8f);
    }
}

// ---------------- Kernel 7: final GEMM, f32x2, 64x64 tiles, split-K 6 --------
__global__ void __launch_bounds__(256)
final_gemm(const float* __restrict__ Wout)
{
    __shared__ float AsT[32][68];
    __shared__ float Bs[32][68];
    const int bx = blockIdx.x, by = blockIdx.y, bz = blockIdx.z;
    const int tid = threadIdx.x;
    const int ty = tid >> 4, tx = tid & 15;
    const int kbeg = bz * 352;

    ull acc[4][2];
    #pragma unroll
    for (int rr = 0; rr < 4; rr++) { acc[rr][0] = 0ULL; acc[rr][1] = 0ULL; }

    for (int kt = kbeg; kt < kbeg + 352; kt += 32) {
        for (int idx = tid; idx < 2048; idx += 256) {
            const int r = idx >> 5, k = idx & 31;
            AsT[k][r] = g_cat[(by*64 + r)*NOUTD + kt + k];
        }
        for (int idx = tid; idx < 2048; idx += 256) {
            const int k = idx >> 6, c = idx & 63;
            Bs[k][c] = Wout[(kt + k)*NCS + bx*64 + c];
        }
        __syncthreads();
        #pragma unroll
        for (int k = 0; k < 32; k++) {
            const float4 a4 = *(const float4*)&AsT[k][ty*4];
            const double2 bd = *(const double2*)&Bs[k][tx*4];
            const ull b01 = LL(bd.x), b23 = LL(bd.y);
            ull d;
            d = pk2(a4.x,a4.x); acc[0][0]=fmaf2(d,b01,acc[0][0]); acc[0][1]=fmaf2(d,b23,acc[0][1]);
            d = pk2(a4.y,a4.y); acc[1][0]=fmaf2(d,b01,acc[1][0]); acc[1][1]=fmaf2(d,b23,acc[1][1]);
            d = pk2(a4.z,a4.z); acc[2][0]=fmaf2(d,b01,acc[2][0]); acc[2][1]=fmaf2(d,b23,acc[2][1]);
            d = pk2(a4.w,a4.w); acc[3][0]=fmaf2(d,b01,acc[3][0]); acc[3][1]=fmaf2(d,b23,acc[3][1]);
        }
        __syncthreads();
    }
    float* dst = g_fpart + (size_t)bz*NTOK*NCS;
    #pragma unroll
    for (int rr = 0; rr < 4; rr++) {
        double2 st = make_double2(DD(acc[rr][0]), DD(acc[rr][1]));
        *(double2*)&dst[(by*64 + ty*4 + rr)*NCS + bx*64 + tx*4] = st;
    }
}

__global__ void final_add(const float* __restrict__ bout, float* __restrict__ out)
{
    const int o = blockIdx.x*256 + threadIdx.x;
    if (o >= NTOK*NCS) return;
    float sv = bout[o % NCS];
    #pragma unroll
    for (int p = 0; p < 6; p++) sv += g_fpart[p*NTOK*NCS + o];
    out[o] = sv;
}

// ---------------- launch ------------------------------------------------------
extern "C" void kernel_launch(void* const* d_in, const int* in_sizes, int n_in,
                              void* d_out, int out_size)
{
    const float* s     = (const float*)d_in[0];
    const float* z     = (const float*)d_in[1];
    const float* rot   = (const float*)d_in[2];
    const float* trans = (const float*)d_in[3];
    const float* mask  = (const float*)d_in[4];
    const float* Wq    = (const float*)d_in[5];
    const float* bq    = (const float*)d_in[6];
    const float* Wkv   = (const float*)d_in[7];
    const float* bkv   = (const float*)d_in[8];
    const float* Wqp   = (const float*)d_in[9];
    const float* bqp   = (const float*)d_in[10];
    const float* Wkvp  = (const float*)d_in[11];
    const float* bkvp  = (const float*)d_in[12];
    const float* Wb    = (const float*)d_in[13];
    const float* bb    = (const float*)d_in[14];
    const float* hwts  = (const float*)d_in[15];
    const float* Wout  = (const float*)d_in[16];
    const float* bout  = (const float*)d_in[17];
    float* out = (float*)d_out;

    proj_kernel<<<dim3(16,19,1), 256>>>(s, Wq,bq, Wkv,bkv, Wqp,bqp, Wkvp,bkvp);
    prep_kernel<<<NTOK, 256>>>(rot, trans, hwts);
    qkbp_kernel<<<768 + 4096, 256>>>(z, Wb, bb);
    softmax_kernel<<<NTOK, 512>>>(mask);            // <- profiled slot (#4)
    opair_ovh<<<512 + 384, 256>>>(z);
    ovh_reduce<<<dim3(16,12,1), 256>>>(rot, trans);
    final_gemm<<<dim3(6,8,6), 256>>>(Wout);
    final_add<<<(NTOK*NCS + 255)/256, 256>>>(bout, out);
}